// round 1
// baseline (speedup 1.0000x reference)
#include <cuda_runtime.h>
#include <math.h>

#define BATCH 4
#define SEQ   2048
#define DMODEL 1024

// ---------------- scratch (static device globals; no allocations) ----------
__device__ float g_Q[BATCH * SEQ * DMODEL];
__device__ float g_K[BATCH * SEQ * DMODEL];
__device__ float g_V[BATCH * SEQ * DMODEL];
__device__ float g_mags[BATCH * SEQ];
__device__ float g_thresh;

// ---------------- per-token L2 norms ---------------------------------------
__global__ void mags_kernel(const float* __restrict__ E) {
    int row = blockIdx.x;                  // 0..B*S-1
    const float4* p = (const float4*)(E + (size_t)row * DMODEL);
    int tid = threadIdx.x;                 // 256 threads, 4 floats each
    float4 v = p[tid];
    float s = v.x * v.x + v.y * v.y + v.z * v.z + v.w * v.w;
    __shared__ float sm[256];
    sm[tid] = s;
    __syncthreads();
    for (int off = 128; off > 0; off >>= 1) {
        if (tid < off) sm[tid] += sm[tid + off];
        __syncthreads();
    }
    if (tid == 0) g_mags[row] = sqrtf(sm[0]);
}

// ---------------- global intent threshold ----------------------------------
// mean over [B,S,S] of mags[b,i]*mags[b,j] == sum_b (sum_i mags[b,i])^2 / (B*S*S)
__global__ void thresh_kernel() {
    int tid = threadIdx.x;                 // single block, 256 threads
    __shared__ double sd[256];
    double total = 0.0;
    for (int b = 0; b < BATCH; b++) {
        double local = 0.0;
        for (int i = tid; i < SEQ; i += 256) local += (double)g_mags[b * SEQ + i];
        sd[tid] = local;
        __syncthreads();
        for (int off = 128; off > 0; off >>= 1) {
            if (tid < off) sd[tid] += sd[tid + off];
            __syncthreads();
        }
        if (tid == 0) total += sd[0] * sd[0];
        __syncthreads();
    }
    if (tid == 0)
        g_thresh = (float)(total / ((double)BATCH * SEQ * SEQ));
}

// ---------------- shared GEMM mainloop -------------------------------------
// C tile [64x64], 256 threads, 4x4 per thread, BK=16.
// BT=true : B is [N,K] row-major (C = A * B^T)
// BT=false: B is [K,N] row-major (C = A * B)
#define BM 64
#define BN 64
#define BK 16
#define PAD 4

template <bool BT>
__device__ __forceinline__ void gemm_main(
    const float* __restrict__ A, const float* __restrict__ B,
    int lda, int ldb, int K, int m0, int n0, float acc[4][4])
{
    __shared__ float As[BK][BM + PAD];
    __shared__ float Bs[BK][BN + PAD];
    int tid = threadIdx.x;
    int tx = tid & 15;        // N direction
    int ty = tid >> 4;        // M direction

    for (int k0 = 0; k0 < K; k0 += BK) {
        {   // A tile: [m0..m0+63] x [k0..k0+15] -> As[k][m] (transposed)
            int m = tid >> 2, kv = tid & 3;
            float4 v = *(const float4*)&A[(size_t)(m0 + m) * lda + k0 + kv * 4];
            As[kv * 4 + 0][m] = v.x;
            As[kv * 4 + 1][m] = v.y;
            As[kv * 4 + 2][m] = v.z;
            As[kv * 4 + 3][m] = v.w;
        }
        if (BT) {
            int n = tid >> 2, kv = tid & 3;
            float4 v = *(const float4*)&B[(size_t)(n0 + n) * ldb + k0 + kv * 4];
            Bs[kv * 4 + 0][n] = v.x;
            Bs[kv * 4 + 1][n] = v.y;
            Bs[kv * 4 + 2][n] = v.z;
            Bs[kv * 4 + 3][n] = v.w;
        } else {
            int kk = tid >> 6, n = tid & 63;
            #pragma unroll
            for (int i = 0; i < 4; i++)
                Bs[kk + i * 4][n] = B[(size_t)(k0 + kk + i * 4) * ldb + n0 + n];
        }
        __syncthreads();

        #pragma unroll
        for (int k = 0; k < BK; k++) {
            float4 a4 = *(const float4*)&As[k][ty * 4];
            float4 b4 = *(const float4*)&Bs[k][tx * 4];
            float av[4] = {a4.x, a4.y, a4.z, a4.w};
            float bv[4] = {b4.x, b4.y, b4.z, b4.w};
            #pragma unroll
            for (int i = 0; i < 4; i++)
                #pragma unroll
                for (int j = 0; j < 4; j++)
                    acc[i][j] += av[i] * bv[j];
        }
        __syncthreads();
    }
}

// ---------------- Q/K/V projections: C = E * W^T ---------------------------
__global__ void qkv_kernel(const float* __restrict__ E,
                           const float* __restrict__ Wq,
                           const float* __restrict__ Wk,
                           const float* __restrict__ Wv)
{
    const float* W = (blockIdx.z == 0) ? Wq : (blockIdx.z == 1) ? Wk : Wv;
    float* C = (blockIdx.z == 0) ? g_Q : (blockIdx.z == 1) ? g_K : g_V;
    int m0 = blockIdx.y * BM, n0 = blockIdx.x * BN;
    float acc[4][4] = {};
    gemm_main<true>(E, W, DMODEL, DMODEL, DMODEL, m0, n0, acc);

    int tx = threadIdx.x & 15, ty = threadIdx.x >> 4;
    #pragma unroll
    for (int i = 0; i < 4; i++) {
        float4 v = make_float4(acc[i][0], acc[i][1], acc[i][2], acc[i][3]);
        *(float4*)&C[(size_t)(m0 + ty * 4 + i) * DMODEL + n0 + tx * 4] = v;
    }
}

// ---------------- scores = Q K^T * inv_scale + intent bias, masked ---------
__global__ void scores_kernel(const float* __restrict__ intent_bias,
                              const int* __restrict__ mask,
                              float* __restrict__ wts)
{
    int b = blockIdx.z;
    const float* A = g_Q + (size_t)b * SEQ * DMODEL;
    const float* Bp = g_K + (size_t)b * SEQ * DMODEL;
    int m0 = blockIdx.y * BM, n0 = blockIdx.x * BN;
    float acc[4][4] = {};
    gemm_main<true>(A, Bp, DMODEL, DMODEL, DMODEL, m0, n0, acc);

    int tx = threadIdx.x & 15, ty = threadIdx.x >> 4;
    float bias = intent_bias[0];
    float th = g_thresh;
    float mq[4], mk[4];
    #pragma unroll
    for (int i = 0; i < 4; i++) mq[i] = g_mags[b * SEQ + m0 + ty * 4 + i];
    #pragma unroll
    for (int j = 0; j < 4; j++) mk[j] = g_mags[b * SEQ + n0 + tx * 4 + j];

    const float inv_scale = 0.03125f;    // 1/sqrt(1024) exact
    #pragma unroll
    for (int i = 0; i < 4; i++) {
        int q = m0 + ty * 4 + i;
        size_t rowbase = ((size_t)b * SEQ + q) * SEQ;
        #pragma unroll
        for (int j = 0; j < 4; j++) {
            int kc = n0 + tx * 4 + j;
            float s = acc[i][j] * inv_scale;
            if (mq[i] * mk[j] > th) s += bias;
            if (mask[rowbase + kc] == 0) s = -1e9f;
            wts[rowbase + kc] = s;
        }
    }
}

// ---------------- row softmax over S=2048, in place -------------------------
__global__ void softmax_kernel(float* __restrict__ w) {
    size_t row = blockIdx.x;
    float4* p = (float4*)(w + row * SEQ);
    int tid = threadIdx.x;                 // 256 threads * 8 elems
    float4 v0 = p[tid];
    float4 v1 = p[tid + 256];
    float m = fmaxf(fmaxf(fmaxf(v0.x, v0.y), fmaxf(v0.z, v0.w)),
                    fmaxf(fmaxf(v1.x, v1.y), fmaxf(v1.z, v1.w)));
    __shared__ float sm[256];
    sm[tid] = m;
    __syncthreads();
    for (int off = 128; off > 0; off >>= 1) {
        if (tid < off) sm[tid] = fmaxf(sm[tid], sm[tid + off]);
        __syncthreads();
    }
    m = sm[0];
    __syncthreads();

    v0.x = expf(v0.x - m); v0.y = expf(v0.y - m);
    v0.z = expf(v0.z - m); v0.w = expf(v0.w - m);
    v1.x = expf(v1.x - m); v1.y = expf(v1.y - m);
    v1.z = expf(v1.z - m); v1.w = expf(v1.w - m);
    float s = v0.x + v0.y + v0.z + v0.w + v1.x + v1.y + v1.z + v1.w;
    sm[tid] = s;
    __syncthreads();
    for (int off = 128; off > 0; off >>= 1) {
        if (tid < off) sm[tid] += sm[tid + off];
        __syncthreads();
    }
    float inv = 1.0f / sm[0];
    v0.x *= inv; v0.y *= inv; v0.z *= inv; v0.w *= inv;
    v1.x *= inv; v1.y *= inv; v1.z *= inv; v1.w *= inv;
    p[tid] = v0;
    p[tid + 256] = v1;
}

// ---------------- attended = P * V  (C = A * B) -----------------------------
__global__ void av_kernel(const float* __restrict__ wts, float* __restrict__ att) {
    int b = blockIdx.z;
    const float* A = wts + (size_t)b * SEQ * SEQ;
    const float* Bp = g_V + (size_t)b * SEQ * DMODEL;
    int m0 = blockIdx.y * BM, n0 = blockIdx.x * BN;
    float acc[4][4] = {};
    gemm_main<false>(A, Bp, SEQ, DMODEL, SEQ, m0, n0, acc);

    int tx = threadIdx.x & 15, ty = threadIdx.x >> 4;
    float* C = att + (size_t)b * SEQ * DMODEL;
    #pragma unroll
    for (int i = 0; i < 4; i++) {
        float4 v = make_float4(acc[i][0], acc[i][1], acc[i][2], acc[i][3]);
        *(float4*)&C[(size_t)(m0 + ty * 4 + i) * DMODEL + n0 + tx * 4] = v;
    }
}

// ---------------- launch ----------------------------------------------------
extern "C" void kernel_launch(void* const* d_in, const int* in_sizes, int n_in,
                              void* d_out, int out_size)
{
    (void)in_sizes; (void)n_in; (void)out_size;
    const float* E    = (const float*)d_in[0];
    const float* Wq   = (const float*)d_in[1];
    const float* Wk   = (const float*)d_in[2];
    const float* Wv   = (const float*)d_in[3];
    const float* bias = (const float*)d_in[4];
    const int*   mask = (const int*)d_in[5];

    float* out = (float*)d_out;
    float* att = out;                                   // [B,S,D]
    float* wts = out + (size_t)BATCH * SEQ * DMODEL;    // [B,S,S]

    mags_kernel<<<BATCH * SEQ, 256>>>(E);
    thresh_kernel<<<1, 256>>>();

    dim3 gQKV(DMODEL / BN, (BATCH * SEQ) / BM, 3);
    qkv_kernel<<<gQKV, 256>>>(E, Wq, Wk, Wv);

    dim3 gS(SEQ / BN, SEQ / BM, BATCH);
    scores_kernel<<<gS, 256>>>(bias, mask, wts);

    softmax_kernel<<<BATCH * SEQ, 256>>>(wts);

    dim3 gAV(DMODEL / BN, SEQ / BM, BATCH);
    av_kernel<<<gAV, 256>>>(wts, att);
}

// round 4
// speedup vs baseline: 2.3139x; 2.3139x over previous
#include <cuda_runtime.h>
#include <cuda_bf16.h>
#include <cstdint>
#include <math.h>

#define BATCH 4
#define SEQ   2048
#define DMODEL 1024

#define ROWB 80                       // smem row stride bytes (32 bf16 + 16B pad)
#define TILE_BYTES (128 * ROWB)       // 10240
#define OFF_AH 0
#define OFF_AL (1 * TILE_BYTES)
#define OFF_BH (2 * TILE_BYTES)
#define OFF_BL (3 * TILE_BYTES)

// ======================= scratch ============================================
__device__ unsigned g_Ep[BATCH * SEQ * DMODEL];      // packed (hi<<16|lo) bf16
__device__ unsigned g_Wp[3 * DMODEL * DMODEL];
__device__ unsigned g_Qp[BATCH * SEQ * DMODEL];
__device__ unsigned g_Kp[BATCH * SEQ * DMODEL];
__device__ unsigned g_Vtp[BATCH * DMODEL * SEQ];     // V transposed [b][d][s]
__device__ unsigned g_Pp[BATCH * SEQ * SEQ];         // softmax weights packed
__device__ float g_mags[BATCH * SEQ];
__device__ float g_thresh;

__device__ __forceinline__ unsigned pack_f32(float x) {
    __nv_bfloat16 h = __float2bfloat16(x);
    float hf = __bfloat162float(h);
    __nv_bfloat16 l = __float2bfloat16(x - hf);
    return ((unsigned)__bfloat16_as_ushort(h) << 16) | (unsigned)__bfloat16_as_ushort(l);
}

__device__ __forceinline__ uint32_t smem_u32(const void* p) {
    uint32_t a;
    asm("{ .reg .u64 t; cvta.to.shared.u64 t, %1; cvt.u32.u64 %0, t; }" : "=r"(a) : "l"(p));
    return a;
}

__device__ __forceinline__ void ldm4(uint32_t f[4], uint32_t addr) {
    asm volatile("ldmatrix.sync.aligned.m8n8.x4.shared.b16 {%0,%1,%2,%3}, [%4];"
        : "=r"(f[0]), "=r"(f[1]), "=r"(f[2]), "=r"(f[3]) : "r"(addr));
}

__device__ __forceinline__ void mma16816(float c[4], const uint32_t a[4],
                                         uint32_t b0, uint32_t b1) {
    asm volatile(
        "mma.sync.aligned.m16n8k16.row.col.f32.bf16.bf16.f32 "
        "{%0,%1,%2,%3}, {%4,%5,%6,%7}, {%8,%9}, {%0,%1,%2,%3};"
        : "+f"(c[0]), "+f"(c[1]), "+f"(c[2]), "+f"(c[3])
        : "r"(a[0]), "r"(a[1]), "r"(a[2]), "r"(a[3]), "r"(b0), "r"(b1));
}

// ======================= small kernels ======================================
__global__ void convert_kernel(const float* __restrict__ src, int which, int n4) {
    int i = blockIdx.x * blockDim.x + threadIdx.x;
    if (i >= n4) return;
    unsigned* dst = (which == 0) ? g_Ep : g_Wp + (size_t)(which - 1) * DMODEL * DMODEL;
    float4 v = ((const float4*)src)[i];
    uint4 o;
    o.x = pack_f32(v.x); o.y = pack_f32(v.y); o.z = pack_f32(v.z); o.w = pack_f32(v.w);
    ((uint4*)dst)[i] = o;
}

__global__ void mags_kernel(const float* __restrict__ E) {
    int row = blockIdx.x;
    const float4* p = (const float4*)(E + (size_t)row * DMODEL);
    int tid = threadIdx.x;
    float4 v = p[tid];
    float s = v.x * v.x + v.y * v.y + v.z * v.z + v.w * v.w;
    __shared__ float sm[256];
    sm[tid] = s;
    __syncthreads();
    for (int off = 128; off > 0; off >>= 1) {
        if (tid < off) sm[tid] += sm[tid + off];
        __syncthreads();
    }
    if (tid == 0) g_mags[row] = sqrtf(sm[0]);
}

__global__ void thresh_kernel() {
    int tid = threadIdx.x;
    __shared__ double sd[256];
    double total = 0.0;
    for (int b = 0; b < BATCH; b++) {
        double local = 0.0;
        for (int i = tid; i < SEQ; i += 256) local += (double)g_mags[b * SEQ + i];
        sd[tid] = local;
        __syncthreads();
        for (int off = 128; off > 0; off >>= 1) {
            if (tid < off) sd[tid] += sd[tid + off];
            __syncthreads();
        }
        if (tid == 0) total += sd[0] * sd[0];
        __syncthreads();
    }
    if (tid == 0) g_thresh = (float)(total / ((double)BATCH * SEQ * SEQ));
}

__global__ void softmax_kernel(float* __restrict__ w) {
    size_t row = blockIdx.x;
    float4* p = (float4*)(w + row * SEQ);
    uint4* pp = (uint4*)(g_Pp + row * SEQ);
    int tid = threadIdx.x;
    float4 v0 = p[tid];
    float4 v1 = p[tid + 256];
    float m = fmaxf(fmaxf(fmaxf(v0.x, v0.y), fmaxf(v0.z, v0.w)),
                    fmaxf(fmaxf(v1.x, v1.y), fmaxf(v1.z, v1.w)));
    __shared__ float sm[256];
    sm[tid] = m;
    __syncthreads();
    for (int off = 128; off > 0; off >>= 1) {
        if (tid < off) sm[tid] = fmaxf(sm[tid], sm[tid + off]);
        __syncthreads();
    }
    m = sm[0];
    __syncthreads();
    v0.x = expf(v0.x - m); v0.y = expf(v0.y - m);
    v0.z = expf(v0.z - m); v0.w = expf(v0.w - m);
    v1.x = expf(v1.x - m); v1.y = expf(v1.y - m);
    v1.z = expf(v1.z - m); v1.w = expf(v1.w - m);
    float s = v0.x + v0.y + v0.z + v0.w + v1.x + v1.y + v1.z + v1.w;
    sm[tid] = s;
    __syncthreads();
    for (int off = 128; off > 0; off >>= 1) {
        if (tid < off) sm[tid] += sm[tid + off];
        __syncthreads();
    }
    float inv = 1.0f / sm[0];
    v0.x *= inv; v0.y *= inv; v0.z *= inv; v0.w *= inv;
    v1.x *= inv; v1.y *= inv; v1.z *= inv; v1.w *= inv;
    p[tid] = v0;
    p[tid + 256] = v1;
    uint4 q0, q1;
    q0.x = pack_f32(v0.x); q0.y = pack_f32(v0.y); q0.z = pack_f32(v0.z); q0.w = pack_f32(v0.w);
    q1.x = pack_f32(v1.x); q1.y = pack_f32(v1.y); q1.z = pack_f32(v1.z); q1.w = pack_f32(v1.w);
    pp[tid] = q0;
    pp[tid + 256] = q1;
}

// ======================= HMMA GEMM core =====================================
// C[128x128] per CTA, 8 warps (2x4) of 64x32, BK=32.
// A [M,K], B [N,K] both packed u32 (hi|lo bf16), K-contiguous.
// 3-product bf16 split: C += Ah*Bh + Ah*Bl + Al*Bh.
__device__ __forceinline__ void gemm_run(
    const unsigned* __restrict__ A, const unsigned* __restrict__ B,
    int lda, int ldb, int K, int m0, int n0, float acc[4][4][4])
{
    __shared__ __align__(16) char sm[4 * TILE_BYTES];
    uint32_t sb = smem_u32(sm);
    int tid = threadIdx.x, lane = tid & 31, warp = tid >> 5;
    int wm = (warp >> 2) * 64, wn = (warp & 3) * 32;
    int row = tid >> 1, half = tid & 1;

    const unsigned* ar = A + (size_t)(m0 + row) * lda + half * 16;
    const unsigned* br = B + (size_t)(n0 + row) * ldb + half * 16;
    uint32_t soff = row * ROWB + half * 32;

    int g = lane >> 3, r = lane & 7;
    uint32_t lm_a = sb + (uint32_t)((wm + (g & 1) * 8 + r) * ROWB + (g >> 1) * 16);
    uint32_t lm_b = sb + OFF_BH + (uint32_t)((wn + (g & 1) * 8 + r) * ROWB + (g >> 1) * 16);

    int NC = K >> 5;
    uint4 av[4], bv[4];
    #pragma unroll
    for (int q = 0; q < 4; q++) {
        av[q] = *(const uint4*)(ar + q * 4);
        bv[q] = *(const uint4*)(br + q * 4);
    }

    for (int c = 0; c < NC; c++) {
        #pragma unroll
        for (int q = 0; q < 4; q++) {
            uint32_t o = soff + q * 8;
            *(uint2*)(sm + OFF_AH + o) = make_uint2(__byte_perm(av[q].x, av[q].y, 0x7632),
                                                   __byte_perm(av[q].z, av[q].w, 0x7632));
            *(uint2*)(sm + OFF_AL + o) = make_uint2(__byte_perm(av[q].x, av[q].y, 0x5410),
                                                   __byte_perm(av[q].z, av[q].w, 0x5410));
            *(uint2*)(sm + OFF_BH + o) = make_uint2(__byte_perm(bv[q].x, bv[q].y, 0x7632),
                                                   __byte_perm(bv[q].z, bv[q].w, 0x7632));
            *(uint2*)(sm + OFF_BL + o) = make_uint2(__byte_perm(bv[q].x, bv[q].y, 0x5410),
                                                   __byte_perm(bv[q].z, bv[q].w, 0x5410));
        }
        __syncthreads();
        if (c + 1 < NC) {
            #pragma unroll
            for (int q = 0; q < 4; q++) {
                av[q] = *(const uint4*)(ar + (c + 1) * 32 + q * 4);
                bv[q] = *(const uint4*)(br + (c + 1) * 32 + q * 4);
            }
        }
        #pragma unroll
        for (int kb = 0; kb < 2; kb++) {
            uint32_t ah[4][4], al[4][4], bh[2][4], bl[2][4];
            #pragma unroll
            for (int mi = 0; mi < 4; mi++) {
                uint32_t ao = lm_a + mi * 16 * ROWB + kb * 32;
                ldm4(ah[mi], ao);
                ldm4(al[mi], ao + OFF_AL);
            }
            #pragma unroll
            for (int nb = 0; nb < 2; nb++) {
                uint32_t bo = lm_b + nb * 16 * ROWB + kb * 32;
                ldm4(bh[nb], bo);
                ldm4(bl[nb], bo + (OFF_BL - OFF_BH));
            }
            #pragma unroll
            for (int mi = 0; mi < 4; mi++)
                #pragma unroll
                for (int nb = 0; nb < 2; nb++)
                    #pragma unroll
                    for (int s = 0; s < 2; s++) {
                        int ni = nb * 2 + s;
                        uint32_t b0h = bh[nb][s], b1h = bh[nb][s + 2];
                        uint32_t b0l = bl[nb][s], b1l = bl[nb][s + 2];
                        mma16816(acc[mi][ni], ah[mi], b0h, b1h);
                        mma16816(acc[mi][ni], ah[mi], b0l, b1l);
                        mma16816(acc[mi][ni], al[mi], b0h, b1h);
                    }
        }
        __syncthreads();
    }
}

// ======================= GEMM kernels =======================================
__global__ void __launch_bounds__(256, 1) qkv_tc(int z_unused) {
    int z = blockIdx.z;
    const unsigned* Bw = g_Wp + (size_t)z * DMODEL * DMODEL;
    int m0 = blockIdx.y * 128, n0 = blockIdx.x * 128;
    float acc[4][4][4] = {};
    gemm_run(g_Ep, Bw, DMODEL, DMODEL, DMODEL, m0, n0, acc);

    int lane = threadIdx.x & 31, warp = threadIdx.x >> 5;
    int wm = (warp >> 2) * 64, wn = (warp & 3) * 32;
    #pragma unroll
    for (int mi = 0; mi < 4; mi++)
        #pragma unroll
        for (int h = 0; h < 2; h++) {
            int rg = m0 + wm + mi * 16 + h * 8 + (lane >> 2);
            #pragma unroll
            for (int ni = 0; ni < 4; ni++) {
                int col = n0 + wn + ni * 8 + (lane & 3) * 2;
                unsigned p0 = pack_f32(acc[mi][ni][h * 2]);
                unsigned p1 = pack_f32(acc[mi][ni][h * 2 + 1]);
                if (z == 2) {
                    int b = rg >> 11, s = rg & (SEQ - 1);
                    unsigned* vb = g_Vtp + (size_t)b * DMODEL * SEQ;
                    vb[(size_t)col * SEQ + s] = p0;
                    vb[(size_t)(col + 1) * SEQ + s] = p1;
                } else {
                    unsigned* C = (z == 0) ? g_Qp : g_Kp;
                    *(uint2*)&C[(size_t)rg * DMODEL + col] = make_uint2(p0, p1);
                }
            }
        }
}

__global__ void __launch_bounds__(256, 1) scores_tc(
    const float* __restrict__ intent_bias, const int* __restrict__ mask,
    float* __restrict__ wts)
{
    int b = blockIdx.z;
    const unsigned* A = g_Qp + (size_t)b * SEQ * DMODEL;
    const unsigned* Bp = g_Kp + (size_t)b * SEQ * DMODEL;
    int m0 = blockIdx.y * 128, n0 = blockIdx.x * 128;
    float acc[4][4][4] = {};
    gemm_run(A, Bp, DMODEL, DMODEL, DMODEL, m0, n0, acc);

    int lane = threadIdx.x & 31, warp = threadIdx.x >> 5;
    int wm = (warp >> 2) * 64, wn = (warp & 3) * 32;
    float th = g_thresh;
    float bias = intent_bias[0];
    #pragma unroll
    for (int mi = 0; mi < 4; mi++)
        #pragma unroll
        for (int h = 0; h < 2; h++) {
            int q = m0 + wm + mi * 16 + h * 8 + (lane >> 2);
            float mq = g_mags[b * SEQ + q];
            size_t rb = ((size_t)b * SEQ + q) * SEQ;
            #pragma unroll
            for (int ni = 0; ni < 4; ni++) {
                int col = n0 + wn + ni * 8 + (lane & 3) * 2;
                float x0 = acc[mi][ni][h * 2] * 0.03125f;
                float x1 = acc[mi][ni][h * 2 + 1] * 0.03125f;
                float mk0 = g_mags[b * SEQ + col];
                float mk1 = g_mags[b * SEQ + col + 1];
                if (mq * mk0 > th) x0 += bias;
                if (mq * mk1 > th) x1 += bias;
                int2 mv = *(const int2*)&mask[rb + col];
                if (mv.x == 0) x0 = -1e9f;
                if (mv.y == 0) x1 = -1e9f;
                *(float2*)&wts[rb + col] = make_float2(x0, x1);
            }
        }
}

__global__ void __launch_bounds__(256, 1) av_tc(float* __restrict__ att) {
    int b = blockIdx.z;
    const unsigned* A = g_Pp + (size_t)b * SEQ * SEQ;
    const unsigned* Bp = g_Vtp + (size_t)b * DMODEL * SEQ;
    int m0 = blockIdx.y * 128, n0 = blockIdx.x * 128;
    float acc[4][4][4] = {};
    gemm_run(A, Bp, SEQ, SEQ, SEQ, m0, n0, acc);

    int lane = threadIdx.x & 31, warp = threadIdx.x >> 5;
    int wm = (warp >> 2) * 64, wn = (warp & 3) * 32;
    #pragma unroll
    for (int mi = 0; mi < 4; mi++)
        #pragma unroll
        for (int h = 0; h < 2; h++) {
            int s = m0 + wm + mi * 16 + h * 8 + (lane >> 2);
            #pragma unroll
            for (int ni = 0; ni < 4; ni++) {
                int col = n0 + wn + ni * 8 + (lane & 3) * 2;
                *(float2*)&att[((size_t)b * SEQ + s) * DMODEL + col] =
                    make_float2(acc[mi][ni][h * 2], acc[mi][ni][h * 2 + 1]);
            }
        }
}

// ======================= launch =============================================
extern "C" void kernel_launch(void* const* d_in, const int* in_sizes, int n_in,
                              void* d_out, int out_size)
{
    (void)in_sizes; (void)n_in; (void)out_size;
    const float* E    = (const float*)d_in[0];
    const float* Wq   = (const float*)d_in[1];
    const float* Wk   = (const float*)d_in[2];
    const float* Wv   = (const float*)d_in[3];
    const float* bias = (const float*)d_in[4];
    const int*   mask = (const int*)d_in[5];

    float* out = (float*)d_out;
    float* att = out;                                  // [B,S,D]
    float* wts = out + (size_t)BATCH * SEQ * DMODEL;   // [B,S,S]

    convert_kernel<<<(BATCH * SEQ * DMODEL / 4 + 255) / 256, 256>>>(E, 0, BATCH * SEQ * DMODEL / 4);
    convert_kernel<<<(DMODEL * DMODEL / 4 + 255) / 256, 256>>>(Wq, 1, DMODEL * DMODEL / 4);
    convert_kernel<<<(DMODEL * DMODEL / 4 + 255) / 256, 256>>>(Wk, 2, DMODEL * DMODEL / 4);
    convert_kernel<<<(DMODEL * DMODEL / 4 + 255) / 256, 256>>>(Wv, 3, DMODEL * DMODEL / 4);

    mags_kernel<<<BATCH * SEQ, 256>>>(E);
    thresh_kernel<<<1, 256>>>();

    dim3 gQKV(DMODEL / 128, (BATCH * SEQ) / 128, 3);
    qkv_tc<<<gQKV, 256>>>(0);

    dim3 gS(SEQ / 128, SEQ / 128, BATCH);
    scores_tc<<<gS, 256>>>(bias, mask, wts);

    softmax_kernel<<<BATCH * SEQ, 256>>>(wts);

    dim3 gAV(DMODEL / 128, SEQ / 128, BATCH);
    av_tc<<<gAV, 256>>>(att);
}